// round 1
// baseline (speedup 1.0000x reference)
#include <cuda_runtime.h>
#include <stdint.h>

#define NB   8
#define NCAM 6
#define NBOX 900
#define ND   48
#define BOXES_PER_BATCH (NCAM*NBOX)        /* 5400  */
#define TOTAL_BOXES     (NB*BOXES_PER_BATCH) /* 43200 */
#define MAXQ 400
#define SORT_N 8192

// Scratch (fully overwritten every call -> deterministic, graph-safe)
__device__ unsigned long long g_bitmap[TOTAL_BOXES];
__device__ float              g_area[TOTAL_BOXES];

struct CamData {
    float f, kf, k02, k12;
    float e00,e01,e02,e03, e10,e11,e12,e13, e20,e21,e22,e23;
    float cx, cy;
};

__device__ __forceinline__ float depth_of(int dd) {
    const float step = 59.0f / 47.0f;            // (MAX_D-MIN_D)/(D-1) in fp32
    if (dd == ND-1) return 60.0f;                // linspace endpoint exact
    return __fadd_rn(__fmul_rn((float)dd, step), 1.0f);
}

__device__ __forceinline__ void load_cam(const float* __restrict__ Kmat,
                                         const float* __restrict__ Emat,
                                         int cam, CamData& cd) {
    float f = Kmat[cam*16 + 0];
    cd.f   = f;
    cd.kf  = 1.0f / f;                 // mirrors LU: diag inverted by division
    cd.k02 = -(400.0f * cd.kf);        // off-diag via multiply
    cd.k12 = -(224.0f * cd.kf);
    const float* e = Emat + cam*16;
    cd.e00=e[0];  cd.e01=e[1];  cd.e02=e[2];  cd.e03=e[3];
    cd.e10=e[4];  cd.e11=e[5];  cd.e12=e[6];  cd.e13=e[7];
    cd.e20=e[8];  cd.e21=e[9];  cd.e22=e[10]; cd.e23=e[11];
}

// points_3d = E @ [Kinv @ (cx*d, cy*d, d), 1]
__device__ __forceinline__ void fwd_point(const CamData& cd, float d,
                                          float& X, float& Y, float& Z) {
    float pcx = cd.kf*(cd.cx*d) + cd.k02*d;
    float pcy = cd.kf*(cd.cy*d) + cd.k12*d;
    X = cd.e00*pcx + cd.e01*pcy + cd.e02*d + cd.e03;
    Y = cd.e10*pcx + cd.e11*pcy + cd.e12*d + cd.e13;
    Z = cd.e20*pcx + cd.e21*pcy + cd.e22*d + cd.e23;
}

// ---------------------------------------------------------------------------
// K1: per-box mask bitmap + area. 8 lanes per box, 6 depths per lane.
// ---------------------------------------------------------------------------
__global__ void __launch_bounds__(256)
k_mask(const float* __restrict__ boxes,
       const float* __restrict__ Kmat,
       const float* __restrict__ Emat)
{
    int tid = blockIdx.x * blockDim.x + threadIdx.x;   // grid sized exactly
    int box_gid = tid >> 3;
    int chunk   = tid & 7;
    if (box_gid >= TOTAL_BOXES) return;

    int b  = box_gid / BOXES_PER_BATCH;
    int bl = box_gid % BOXES_PER_BATCH;
    int c  = bl / NBOX;
    int cam = b*NCAM + c;

    float4 bx = ((const float4*)boxes)[box_gid];
    CamData cd; load_cam(Kmat, Emat, cam, cd);
    cd.cx = (bx.x + bx.z)*0.5f;
    cd.cy = (bx.y + bx.w)*0.5f;

    float area = (bx.z - bx.x)*(bx.w - bx.y);
    bool valid = (area > 5.0f) && (area < 197120.0f);  // 800*448*0.55

    // Einv (rigid): Rinv = R^T, tinv = -R^T t ; bottom row exact -> pch3 = 1
    float i00=cd.e00, i01=cd.e10, i02=cd.e20;
    float i10=cd.e01, i11=cd.e11, i12=cd.e21;
    float i20=cd.e02, i21=cd.e12, i22=cd.e22;
    float t0=cd.e03, t1=cd.e13, t2=cd.e23;
    float ti0 = -(i00*t0 + i01*t1 + i02*t2);
    float ti1 = -(i10*t0 + i11*t1 + i12*t2);
    float ti2 = -(i20*t0 + i21*t1 + i22*t2);

    const float ONE_EPS = 1.0f + 1e-6f;

    unsigned long long bmp = 0ull;
    #pragma unroll
    for (int r = 0; r < 6; r++) {
        int dd = chunk*6 + r;
        float d = depth_of(dd);
        float X,Y,Z;
        fwd_point(cd, d, X, Y, Z);
        // re-project
        float p0 = i00*X + i01*Y + i02*Z + ti0;
        float p1 = i10*X + i11*Y + i12*Z + ti1;
        float p2 = i20*X + i21*Y + i22*Z + ti2;
        float pc0 = p0 / ONE_EPS, pc1 = p1 / ONE_EPS, pc2 = p2 / ONE_EPS;
        float pih0 = cd.f*pc0 + 400.0f*pc2;
        float pih1 = cd.f*pc1 + 224.0f*pc2;
        float zd = pc2 + 1e-6f;                 // shared by img and box_size
        float imgx = pih0 / zd;
        float imgy = pih1 / zd;
        float bs = fminf(fmaxf(40.0f * (10.0f / zd), 8.0f), 200.0f);
        float half = bs * 0.5f;
        float px0 = imgx - half, py0 = imgy - half;
        float px1 = imgx + half, py1 = imgy + half;
        float xx1 = fmaxf(px0, bx.x);
        float yy1 = fmaxf(py0, bx.y);
        float xx2 = fminf(px1, bx.z);
        float yy2 = fminf(py1, bx.w);
        float inter = fmaxf(xx2-xx1, 0.0f) * fmaxf(yy2-yy1, 0.0f);
        float a1 = (px1-px0)*(py1-py0);
        float iou = inter / (a1 + area - inter + 1e-6f);
        if ((iou > 0.05f) && valid) bmp |= (1ull << dd);
    }
    bmp |= __shfl_xor_sync(0xffffffffu, bmp, 1);
    bmp |= __shfl_xor_sync(0xffffffffu, bmp, 2);
    bmp |= __shfl_xor_sync(0xffffffffu, bmp, 4);
    if (chunk == 0) {
        g_bitmap[box_gid] = bmp;
        g_area[box_gid]   = area;
    }
}

// ---------------------------------------------------------------------------
// K2: per-batch selection (one block per batch) + output write.
// key64 = areaBits<<32 | (0x3FFF - boxIdx)<<6 | cnt   (larger = better)
// ---------------------------------------------------------------------------
__global__ void __launch_bounds__(1024)
k_select(const float* __restrict__ boxes,
         const float* __restrict__ Kmat,
         const float* __restrict__ Emat,
         float* __restrict__ out, int out_size)
{
    extern __shared__ unsigned char smem_raw[];
    unsigned long long* skey = (unsigned long long*)smem_raw;           // 8192
    int* sscan = (int*)(smem_raw + SORT_N*8);                           // 1024
    int* ssel  = (int*)(smem_raw + SORT_N*8 + 1024*4);                  // 400
    __shared__ int s_total;

    int b   = blockIdx.x;
    int tid = threadIdx.x;
    if (tid == 0) s_total = 0;
    __syncthreads();

    int my = 0;
    for (int i = tid; i < SORT_N; i += 1024) {
        unsigned long long key = 0;
        if (i < BOXES_PER_BATCH) {
            unsigned long long bm = g_bitmap[b*BOXES_PER_BATCH + i];
            int cnt = __popcll(bm);
            if (cnt > 0) {
                unsigned abits = __float_as_uint(g_area[b*BOXES_PER_BATCH + i]);
                unsigned low = ((unsigned)(0x3FFF - i) << 6) | (unsigned)cnt;
                key = ((unsigned long long)abits << 32) | (unsigned long long)low;
                my += cnt;
            }
        }
        skey[i] = key;
    }
    atomicAdd(&s_total, my);
    __syncthreads();
    int total = s_total;

    if (total > MAXQ) {
        // bitonic sort descending (8192 slots, 1024 threads)
        for (unsigned k = 2; k <= SORT_N; k <<= 1) {
            for (unsigned j = k >> 1; j > 0; j >>= 1) {
                for (unsigned p = tid; p < SORT_N; p += 1024) {
                    unsigned q = p ^ j;
                    if (q > p) {
                        unsigned long long a = skey[p], bb = skey[q];
                        bool descBlk = ((p & k) == 0);
                        if (descBlk ? (a < bb) : (a > bb)) { skey[p]=bb; skey[q]=a; }
                    }
                }
                __syncthreads();
            }
        }
    }
    // else: natural box-index order == ascending global index (reference's
    // key_order path). Same scan/expand code works on unsorted slots.

    // thread owns 8 consecutive slots; block scan of counts
    int base_idx = tid * 8;
    int cnts[8];
    int lsum = 0;
    #pragma unroll
    for (int r = 0; r < 8; r++) {
        unsigned long long key = skey[base_idx + r];
        int cnt = key ? (int)(key & 63ull) : 0;
        cnts[r] = cnt;
        lsum += cnt;
    }
    sscan[tid] = lsum;
    __syncthreads();
    for (int off = 1; off < 1024; off <<= 1) {
        int v = (tid >= off) ? sscan[tid - off] : 0;
        __syncthreads();
        sscan[tid] += v;
        __syncthreads();
    }
    int start = sscan[tid] - lsum;   // exclusive prefix

    #pragma unroll
    for (int r = 0; r < 8; r++) {
        int cnt = cnts[r];
        if (cnt > 0 && start < MAXQ) {
            unsigned long long key = skey[base_idx + r];
            int boxLocal = 0x3FFF - (int)((key >> 6) & 0x3FFFull);
            unsigned long long bm = g_bitmap[b*BOXES_PER_BATCH + boxLocal];
            int take = min(cnt, MAXQ - start);
            for (int t = 0; t < take; t++) {
                int d = __ffsll((long long)bm) - 1;   // depths ascending = index asc
                bm &= bm - 1;
                ssel[start + t] = (boxLocal << 6) | d;
            }
        }
        start += cnt;
    }
    __syncthreads();

    // output
    int filled = min(total, MAXQ);
    if (tid < MAXQ) {
        const float DENOM = (float)(102.400001);   // rounds to float(102.4)
        float rx, ry, rz, pm;
        if (tid < filled) {
            int v = ssel[tid];
            int boxLocal = v >> 6;
            int dd = v & 63;
            int box_gid = b*BOXES_PER_BATCH + boxLocal;
            int c = boxLocal / NBOX;
            int cam = b*NCAM + c;
            float4 bx = ((const float4*)boxes)[box_gid];
            CamData cd; load_cam(Kmat, Emat, cam, cd);
            cd.cx = (bx.x + bx.z)*0.5f;
            cd.cy = (bx.y + bx.w)*0.5f;
            float d = depth_of(dd);
            float X,Y,Z; fwd_point(cd, d, X, Y, Z);
            rx = fminf(fmaxf((X + 51.2f)/DENOM, 0.0f), 1.0f);
            ry = fminf(fmaxf((Y + 51.2f)/DENOM, 0.0f), 1.0f);
            rz = fminf(fmaxf((Z + 51.2f)/DENOM, 0.0f), 1.0f);
            pm = 0.0f;
        } else {
            float pad = fminf(fmaxf(51.2f/DENOM, 0.0f), 1.0f);  // sel=0 path
            rx = ry = rz = pad;
            pm = 1.0f;
        }
        int rbase = (b*MAXQ + tid)*3;
        out[rbase + 0] = rx;
        out[rbase + 1] = ry;
        out[rbase + 2] = rz;
        if (out_size >= NB*MAXQ*4)                  // pad_mask appended as floats
            out[NB*MAXQ*3 + b*MAXQ + tid] = pm;
    }
}

// ---------------------------------------------------------------------------
extern "C" void kernel_launch(void* const* d_in, const int* in_sizes, int n_in,
                              void* d_out, int out_size)
{
    const float* boxes = (const float*)d_in[0];   // (8,6,900,4)
    const float* Kmat  = (const float*)d_in[1];   // (8,6,4,4)
    const float* Emat  = (const float*)d_in[2];   // (8,6,4,4)
    float* out = (float*)d_out;

    const int smem_bytes = SORT_N*8 + 1024*4 + MAXQ*4;   // 71232 B
    cudaFuncSetAttribute(k_select, cudaFuncAttributeMaxDynamicSharedMemorySize,
                         smem_bytes);

    k_mask<<<(TOTAL_BOXES*8)/256, 256>>>(boxes, Kmat, Emat);
    k_select<<<NB, 1024, smem_bytes>>>(boxes, Kmat, Emat, out, out_size);
}

// round 2
// speedup vs baseline: 3.4697x; 3.4697x over previous
#include <cuda_runtime.h>
#include <stdint.h>

#define NB   8
#define NCAM 6
#define NBOX 900
#define ND   48
#define BPB  (NCAM*NBOX)            /* 5400  */
#define TOTAL_BOXES (NB*BPB)        /* 43200 */
#define MAXQ 400

// Scratch (fully overwritten every call -> deterministic, graph-safe)
__device__ unsigned long long g_bitmap[TOTAL_BOXES];
__device__ float              g_area[TOTAL_BOXES];

struct CamData {
    float f, kf, k02, k12;
    float e00,e01,e02,e03, e10,e11,e12,e13, e20,e21,e22,e23;
    float cx, cy;
};

__device__ __forceinline__ float depth_of(int dd) {
    const float step = 59.0f / 47.0f;            // (MAX_D-MIN_D)/(D-1) in fp32
    if (dd == ND-1) return 60.0f;                // linspace endpoint exact
    return __fadd_rn(__fmul_rn((float)dd, step), 1.0f);
}

__device__ __forceinline__ void load_cam(const float* __restrict__ Kmat,
                                         const float* __restrict__ Emat,
                                         int cam, CamData& cd) {
    float f = Kmat[cam*16 + 0];
    cd.f   = f;
    cd.kf  = 1.0f / f;                 // mirrors LU: diag inverted by division
    cd.k02 = -(400.0f * cd.kf);
    cd.k12 = -(224.0f * cd.kf);
    const float* e = Emat + cam*16;
    cd.e00=e[0];  cd.e01=e[1];  cd.e02=e[2];  cd.e03=e[3];
    cd.e10=e[4];  cd.e11=e[5];  cd.e12=e[6];  cd.e13=e[7];
    cd.e20=e[8];  cd.e21=e[9];  cd.e22=e[10]; cd.e23=e[11];
}

// points_3d = E @ [Kinv @ (cx*d, cy*d, d), 1]
__device__ __forceinline__ void fwd_point(const CamData& cd, float d,
                                          float& X, float& Y, float& Z) {
    float pcx = cd.kf*(cd.cx*d) + cd.k02*d;
    float pcy = cd.kf*(cd.cy*d) + cd.k12*d;
    X = cd.e00*pcx + cd.e01*pcy + cd.e02*d + cd.e03;
    Y = cd.e10*pcx + cd.e11*pcy + cd.e12*d + cd.e13;
    Z = cd.e20*pcx + cd.e21*pcy + cd.e22*d + cd.e23;
}

// ---------------------------------------------------------------------------
// K1: per-box mask bitmap + area. 8 lanes per box, 6 depths per lane.
// ---------------------------------------------------------------------------
__global__ void __launch_bounds__(256)
k_mask(const float* __restrict__ boxes,
       const float* __restrict__ Kmat,
       const float* __restrict__ Emat)
{
    int tid = blockIdx.x * blockDim.x + threadIdx.x;   // grid sized exactly
    int box_gid = tid >> 3;
    int chunk   = tid & 7;
    if (box_gid >= TOTAL_BOXES) return;

    int b  = box_gid / BPB;
    int bl = box_gid % BPB;
    int c  = bl / NBOX;
    int cam = b*NCAM + c;

    float4 bx = ((const float4*)boxes)[box_gid];
    CamData cd; load_cam(Kmat, Emat, cam, cd);
    cd.cx = (bx.x + bx.z)*0.5f;
    cd.cy = (bx.y + bx.w)*0.5f;

    float area = (bx.z - bx.x)*(bx.w - bx.y);
    bool valid = (area > 5.0f) && (area < 197120.0f);  // 800*448*0.55

    // Einv (rigid): Rinv = R^T, tinv = -R^T t ; bottom row exact -> pch3 = 1
    float i00=cd.e00, i01=cd.e10, i02=cd.e20;
    float i10=cd.e01, i11=cd.e11, i12=cd.e21;
    float i20=cd.e02, i21=cd.e12, i22=cd.e22;
    float t0=cd.e03, t1=cd.e13, t2=cd.e23;
    float ti0 = -(i00*t0 + i01*t1 + i02*t2);
    float ti1 = -(i10*t0 + i11*t1 + i12*t2);
    float ti2 = -(i20*t0 + i21*t1 + i22*t2);

    const float INV_ONE_EPS = 1.0f / (1.0f + 1e-6f);   // compile-time constant

    unsigned long long bmp = 0ull;
    #pragma unroll
    for (int r = 0; r < 6; r++) {
        int dd = chunk*6 + r;
        float d = depth_of(dd);
        float X,Y,Z;
        fwd_point(cd, d, X, Y, Z);
        // re-project
        float p0 = i00*X + i01*Y + i02*Z + ti0;
        float p1 = i10*X + i11*Y + i12*Z + ti1;
        float p2 = i20*X + i21*Y + i22*Z + ti2;
        float pc0 = p0 * INV_ONE_EPS;
        float pc1 = p1 * INV_ONE_EPS;
        float pc2 = p2 * INV_ONE_EPS;
        float pih0 = cd.f*pc0 + 400.0f*pc2;
        float pih1 = cd.f*pc1 + 224.0f*pc2;
        float zd = pc2 + 1e-6f;
        float invzd = 1.0f / zd;                // one exact division
        float imgx = pih0 * invzd;
        float imgy = pih1 * invzd;
        float bs = fminf(fmaxf(40.0f * (10.0f * invzd), 8.0f), 200.0f);
        float half = bs * 0.5f;
        float px0 = imgx - half, py0 = imgy - half;
        float px1 = imgx + half, py1 = imgy + half;
        float xx1 = fmaxf(px0, bx.x);
        float yy1 = fmaxf(py0, bx.y);
        float xx2 = fminf(px1, bx.z);
        float yy2 = fminf(py1, bx.w);
        float inter = fmaxf(xx2-xx1, 0.0f) * fmaxf(yy2-yy1, 0.0f);
        float a1 = (px1-px0)*(py1-py0);
        float iou = inter / (a1 + area - inter + 1e-6f);   // exact: threshold-sensitive
        if ((iou > 0.05f) && valid) bmp |= (1ull << dd);
    }
    bmp |= __shfl_xor_sync(0xffffffffu, bmp, 1);
    bmp |= __shfl_xor_sync(0xffffffffu, bmp, 2);
    bmp |= __shfl_xor_sync(0xffffffffu, bmp, 4);
    if (chunk == 0) {
        g_bitmap[box_gid] = bmp;
        g_area[box_gid]   = area;
    }
}

// ---------------------------------------------------------------------------
// K2: per-batch selection via exact weighted radix-select (no full sort).
// key64 = areaBits<<32 | (0x3FFF - boxIdx)<<6 | cnt   (larger = better, unique)
// ---------------------------------------------------------------------------
__global__ void __launch_bounds__(1024)
k_select(const float* __restrict__ boxes,
         const float* __restrict__ Kmat,
         const float* __restrict__ Emat,
         float* __restrict__ out, int out_size)
{
    extern __shared__ unsigned char sm[];
    unsigned long long* skey = (unsigned long long*)sm;                   // 5400*8
    int* sscan = (int*)(sm + BPB*8);                                      // 1024*4
    unsigned long long* swin = (unsigned long long*)(sm + BPB*8 + 4096);  // 400*8
    int* ssel  = (int*)(sm + BPB*8 + 4096 + 3200);                        // 400*4
    __shared__ int hist[256];
    __shared__ int s_total, s_byte, s_needed, s_wcount;

    int b   = blockIdx.x;
    int tid = threadIdx.x;
    if (tid == 0) { s_total = 0; s_wcount = 0; }
    __syncthreads();

    // Build composite keys
    int my = 0;
    for (int i = tid; i < BPB; i += 1024) {
        unsigned long long bm = g_bitmap[b*BPB + i];
        int cnt = __popcll(bm);
        unsigned long long key = 0;
        if (cnt) {
            unsigned abits = __float_as_uint(g_area[b*BPB + i]);
            key = ((unsigned long long)abits << 32)
                | ((unsigned long long)(0x3FFFu - (unsigned)i) << 6)
                | (unsigned)cnt;
            my += cnt;
        }
        skey[i] = key;
    }
    if (my) atomicAdd(&s_total, my);
    __syncthreads();
    int total  = s_total;
    int filled = min(total, MAXQ);

    if (total > MAXQ) {
        // ---- exact weighted MSD radix-select for the 400th entry's key ----
        unsigned long long prefix = 0, pmask = 0;
        int needed = MAXQ;
        for (int level = 7; level >= 0; --level) {
            if (tid < 256) hist[tid] = 0;
            __syncthreads();
            for (int i = tid; i < BPB; i += 1024) {
                unsigned long long key = skey[i];
                if (key && (key & pmask) == prefix)
                    atomicAdd(&hist[(int)((key >> (level*8)) & 255)],
                              (int)(key & 63));
            }
            __syncthreads();
            // inclusive suffix-sum of hist into sscan[0..255]
            if (tid < 256) sscan[tid] = hist[tid];
            __syncthreads();
            for (int off = 1; off < 256; off <<= 1) {
                int v = 0;
                if (tid < 256 && tid + off < 256) v = sscan[tid + off];
                __syncthreads();
                if (tid < 256) sscan[tid] += v;
                __syncthreads();
            }
            if (tid < 256) {
                int hi = (tid == 255) ? 0 : sscan[tid + 1];
                if (sscan[tid] >= needed && hi < needed) {
                    s_byte = tid; s_needed = needed - hi;
                }
            }
            __syncthreads();
            prefix |= ((unsigned long long)s_byte) << (level*8);
            pmask  |= (0xFFull << (level*8));
            needed  = s_needed;
            __syncthreads();
        }
        unsigned long long T = prefix;   // exact boundary key (unique)

        // ---- compact winners: key >= T, W <= 400 ----
        for (int i = tid; i < BPB; i += 1024) {
            unsigned long long key = skey[i];
            if (key >= T) {
                int p = atomicAdd(&s_wcount, 1);
                swin[p] = key;
            }
        }
        __syncthreads();
        int W = s_wcount;

        // ---- per-winner rank (O(W^2), W<=400, 1 winner/thread) + expand ----
        for (int w = tid; w < W; w += 1024) {
            unsigned long long key = swin[w];
            int off = 0;
            for (int v = 0; v < W; v++) {
                unsigned long long kv = swin[v];
                if (kv > key) off += (int)(kv & 63);
            }
            int boxLocal = 0x3FFF - (int)((key >> 6) & 0x3FFFull);
            unsigned long long bm = g_bitmap[b*BPB + boxLocal];
            int cnt  = (int)(key & 63);
            int take = min(cnt, MAXQ - off);
            for (int t = 0; t < take; t++) {
                int d = __ffsll((long long)bm) - 1;  // depths asc = index asc
                bm &= bm - 1;
                ssel[off + t] = (boxLocal << 6) | d;
            }
        }
    } else {
        // ---- index-order path: block scan of counts, then expand ----
        int base = tid * 6;              // 1024*6 >= 5400
        int cnts[6];
        int lsum = 0;
        #pragma unroll
        for (int r = 0; r < 6; r++) {
            int i = base + r;
            int c = (i < BPB) ? (int)(skey[i] & 63ull) : 0;
            cnts[r] = c; lsum += c;
        }
        sscan[tid] = lsum;
        __syncthreads();
        for (int off = 1; off < 1024; off <<= 1) {
            int v = (tid >= off) ? sscan[tid - off] : 0;
            __syncthreads();
            sscan[tid] += v;
            __syncthreads();
        }
        int start = sscan[tid] - lsum;   // exclusive prefix
        #pragma unroll
        for (int r = 0; r < 6; r++) {
            int i = base + r;
            int cnt = cnts[r];
            if (cnt) {
                unsigned long long bm = g_bitmap[b*BPB + i];
                for (int t = 0; t < cnt; t++) {
                    int d = __ffsll((long long)bm) - 1;
                    bm &= bm - 1;
                    ssel[start + t] = (i << 6) | d;
                }
                start += cnt;
            }
        }
    }
    __syncthreads();

    // ---- output ----
    if (tid < MAXQ) {
        const float DENOM = (float)(102.400001);
        float rx, ry, rz, pm;
        if (tid < filled) {
            int v = ssel[tid];
            int boxLocal = v >> 6;
            int dd = v & 63;
            int box_gid = b*BPB + boxLocal;
            int c = boxLocal / NBOX;
            int cam = b*NCAM + c;
            float4 bx = ((const float4*)boxes)[box_gid];
            CamData cd; load_cam(Kmat, Emat, cam, cd);
            cd.cx = (bx.x + bx.z)*0.5f;
            cd.cy = (bx.y + bx.w)*0.5f;
            float d = depth_of(dd);
            float X,Y,Z; fwd_point(cd, d, X, Y, Z);
            rx = fminf(fmaxf((X + 51.2f)/DENOM, 0.0f), 1.0f);
            ry = fminf(fmaxf((Y + 51.2f)/DENOM, 0.0f), 1.0f);
            rz = fminf(fmaxf((Z + 51.2f)/DENOM, 0.0f), 1.0f);
            pm = 0.0f;
        } else {
            float pad = fminf(fmaxf(51.2f/DENOM, 0.0f), 1.0f);  // sel=0 path
            rx = ry = rz = pad;
            pm = 1.0f;
        }
        int rbase = (b*MAXQ + tid)*3;
        out[rbase + 0] = rx;
        out[rbase + 1] = ry;
        out[rbase + 2] = rz;
        if (out_size >= NB*MAXQ*4)
            out[NB*MAXQ*3 + b*MAXQ + tid] = pm;
    }
}

// ---------------------------------------------------------------------------
extern "C" void kernel_launch(void* const* d_in, const int* in_sizes, int n_in,
                              void* d_out, int out_size)
{
    const float* boxes = (const float*)d_in[0];   // (8,6,900,4)
    const float* Kmat  = (const float*)d_in[1];   // (8,6,4,4)
    const float* Emat  = (const float*)d_in[2];   // (8,6,4,4)
    float* out = (float*)d_out;

    const int smem_bytes = BPB*8 + 1024*4 + MAXQ*8 + MAXQ*4;   // 52096 B
    cudaFuncSetAttribute(k_select, cudaFuncAttributeMaxDynamicSharedMemorySize,
                         smem_bytes);

    k_mask<<<(TOTAL_BOXES*8)/256, 256>>>(boxes, Kmat, Emat);
    k_select<<<NB, 1024, smem_bytes>>>(boxes, Kmat, Emat, out, out_size);
}

// round 3
// speedup vs baseline: 4.9451x; 1.4252x over previous
#include <cuda_runtime.h>
#include <stdint.h>

#define NB   8
#define NCAM 6
#define NBOX 900
#define ND   48
#define BPB  (NCAM*NBOX)            /* 5400  */
#define TOTAL_BOXES (NB*BPB)        /* 43200 */
#define MAXQ 400

typedef unsigned long long u64;

// Scratch (fully overwritten every call -> deterministic, graph-safe)
__device__ u64 g_bitmap[TOTAL_BOXES];
__device__ u64 g_key[TOTAL_BOXES];

struct CamData {
    float f, kf, k02, k12;
    float e00,e01,e02,e03, e10,e11,e12,e13, e20,e21,e22,e23;
    float cx, cy;
};

__device__ __forceinline__ float depth_of(int dd) {
    const float step = 59.0f / 47.0f;            // (MAX_D-MIN_D)/(D-1) in fp32
    if (dd == ND-1) return 60.0f;                // linspace endpoint exact
    return __fadd_rn(__fmul_rn((float)dd, step), 1.0f);
}

__device__ __forceinline__ void load_cam(const float* __restrict__ Kmat,
                                         const float* __restrict__ Emat,
                                         int cam, CamData& cd) {
    float f = Kmat[cam*16 + 0];
    cd.f   = f;
    cd.kf  = 1.0f / f;                 // mirrors LU: diag inverted by division
    cd.k02 = -(400.0f * cd.kf);
    cd.k12 = -(224.0f * cd.kf);
    const float* e = Emat + cam*16;
    cd.e00=e[0];  cd.e01=e[1];  cd.e02=e[2];  cd.e03=e[3];
    cd.e10=e[4];  cd.e11=e[5];  cd.e12=e[6];  cd.e13=e[7];
    cd.e20=e[8];  cd.e21=e[9];  cd.e22=e[10]; cd.e23=e[11];
}

// points_3d = E @ [Kinv @ (cx*d, cy*d, d), 1]
__device__ __forceinline__ void fwd_point(const CamData& cd, float d,
                                          float& X, float& Y, float& Z) {
    float pcx = cd.kf*(cd.cx*d) + cd.k02*d;
    float pcy = cd.kf*(cd.cy*d) + cd.k12*d;
    X = cd.e00*pcx + cd.e01*pcy + cd.e02*d + cd.e03;
    Y = cd.e10*pcx + cd.e11*pcy + cd.e12*d + cd.e13;
    Z = cd.e20*pcx + cd.e21*pcy + cd.e22*d + cd.e23;
}

// ---------------------------------------------------------------------------
// K1: per-box mask bitmap + composite key. 8 lanes/box, 6 depths/lane.
// key64 = areaBits<<32 | (0x3FFF - boxIdx)<<6 | cnt   (larger = better, unique)
// ---------------------------------------------------------------------------
__global__ void __launch_bounds__(256)
k_mask(const float* __restrict__ boxes,
       const float* __restrict__ Kmat,
       const float* __restrict__ Emat)
{
    int tid = blockIdx.x * blockDim.x + threadIdx.x;   // grid sized exactly
    int box_gid = tid >> 3;
    int chunk   = tid & 7;
    if (box_gid >= TOTAL_BOXES) return;

    int b  = box_gid / BPB;
    int bl = box_gid % BPB;
    int c  = bl / NBOX;
    int cam = b*NCAM + c;

    float4 bx = ((const float4*)boxes)[box_gid];
    CamData cd; load_cam(Kmat, Emat, cam, cd);
    cd.cx = (bx.x + bx.z)*0.5f;
    cd.cy = (bx.y + bx.w)*0.5f;

    float area = (bx.z - bx.x)*(bx.w - bx.y);
    bool valid = (area > 5.0f) && (area < 197120.0f);  // 800*448*0.55

    // Einv (rigid): Rinv = R^T, tinv = -R^T t ; bottom row exact -> pch3 = 1
    float i00=cd.e00, i01=cd.e10, i02=cd.e20;
    float i10=cd.e01, i11=cd.e11, i12=cd.e21;
    float i20=cd.e02, i21=cd.e12, i22=cd.e22;
    float t0=cd.e03, t1=cd.e13, t2=cd.e23;
    float ti0 = -(i00*t0 + i01*t1 + i02*t2);
    float ti1 = -(i10*t0 + i11*t1 + i12*t2);
    float ti2 = -(i20*t0 + i21*t1 + i22*t2);

    const float INV_ONE_EPS = 1.0f / (1.0f + 1e-6f);

    u64 bmp = 0ull;
    #pragma unroll
    for (int r = 0; r < 6; r++) {
        int dd = chunk*6 + r;
        float d = depth_of(dd);
        float X,Y,Z;
        fwd_point(cd, d, X, Y, Z);
        float p0 = i00*X + i01*Y + i02*Z + ti0;
        float p1 = i10*X + i11*Y + i12*Z + ti1;
        float p2 = i20*X + i21*Y + i22*Z + ti2;
        float pc0 = p0 * INV_ONE_EPS;
        float pc1 = p1 * INV_ONE_EPS;
        float pc2 = p2 * INV_ONE_EPS;
        float pih0 = cd.f*pc0 + 400.0f*pc2;
        float pih1 = cd.f*pc1 + 224.0f*pc2;
        float zd = pc2 + 1e-6f;
        float invzd = 1.0f / zd;
        float imgx = pih0 * invzd;
        float imgy = pih1 * invzd;
        float bs = fminf(fmaxf(40.0f * (10.0f * invzd), 8.0f), 200.0f);
        float half = bs * 0.5f;
        float px0 = imgx - half, py0 = imgy - half;
        float px1 = imgx + half, py1 = imgy + half;
        float xx1 = fmaxf(px0, bx.x);
        float yy1 = fmaxf(py0, bx.y);
        float xx2 = fminf(px1, bx.z);
        float yy2 = fminf(py1, bx.w);
        float inter = fmaxf(xx2-xx1, 0.0f) * fmaxf(yy2-yy1, 0.0f);
        float a1 = (px1-px0)*(py1-py0);
        float iou = inter / (a1 + area - inter + 1e-6f);   // exact: threshold-sensitive
        if ((iou > 0.05f) && valid) bmp |= (1ull << dd);
    }
    bmp |= __shfl_xor_sync(0xffffffffu, bmp, 1);
    bmp |= __shfl_xor_sync(0xffffffffu, bmp, 2);
    bmp |= __shfl_xor_sync(0xffffffffu, bmp, 4);
    if (chunk == 0) {
        g_bitmap[box_gid] = bmp;
        int cnt = __popcll(bmp);
        u64 key = 0;
        if (cnt)
            key = ((u64)__float_as_uint(area) << 32)
                | ((u64)(0x3FFFu - (unsigned)bl) << 6)
                | (unsigned)cnt;
        g_key[box_gid] = key;
    }
}

// ---------------------------------------------------------------------------
// K2: per-batch selection. Weighted MSD radix-select with per-level
// compaction + warp-scanned histogram (few barriers), then O(W^2) rank.
// ---------------------------------------------------------------------------
__global__ void __launch_bounds__(1024)
k_select(const float* __restrict__ boxes,
         const float* __restrict__ Kmat,
         const float* __restrict__ Emat,
         float* __restrict__ out, int out_size)
{
    extern __shared__ unsigned char sm[];
    u64* A    = (u64*)sm;                         // 5400 keys
    u64* Bb   = A + BPB;                          // 5400 keys (ping-pong)
    u64* swin = Bb + BPB;                         // 400 winners
    int* ssel = (int*)(swin + MAXQ);              // 400 selections
    __shared__ int hist[256];
    __shared__ int s_cnt, s_total, s_byte, s_needed;

    int b   = blockIdx.x;
    int tid = threadIdx.x;
    if (tid == 0) { s_cnt = 0; s_total = 0; }
    __syncthreads();

    // phase 1: compact nonzero keys, accumulate total expanded count
    int my = 0;
    for (int i = tid; i < BPB; i += 1024) {
        u64 key = g_key[b*BPB + i];
        if (key) {
            A[atomicAdd(&s_cnt, 1)] = key;
            my += (int)(key & 63ull);
        }
    }
    if (my) atomicAdd(&s_total, my);
    __syncthreads();
    int total  = s_total;
    int nA     = s_cnt;
    int filled = min(total, MAXQ);
    int W      = 0;

    if (total > MAXQ) {
        // ---- weighted MSD radix-select with compaction ----
        u64 *src = A, *dst = Bb;
        int needed = MAXQ;
        for (int level = 7; level >= 0 && nA > 1; --level) {
            int shift = level * 8;
            if (tid < 256) hist[tid] = 0;
            if (tid == 0)  s_cnt = 0;
            __syncthreads();
            for (int i = tid; i < nA; i += 1024)
                atomicAdd(&hist[(int)((src[i] >> shift) & 255)],
                          (int)(src[i] & 63ull));
            __syncthreads();
            if (tid < 32) {
                // warp 0: 8 bins per lane, suffix-sum, find boundary bucket
                int s[8]; int lt = 0;
                #pragma unroll
                for (int j = 0; j < 8; j++) { s[j] = hist[tid*8 + j]; lt += s[j]; }
                int suf = lt;
                #pragma unroll
                for (int off = 1; off < 32; off <<= 1) {
                    int v = __shfl_down_sync(0xffffffffu, suf, off);
                    if (tid + off < 32) suf += v;
                }
                int run = suf - lt;                // sum over lanes > tid
                #pragma unroll
                for (int j = 7; j >= 0; j--) {
                    int S = run + s[j];            // suffix sum from bin j
                    if (S >= needed && run < needed) {
                        s_byte = tid*8 + j;
                        s_needed = needed - run;
                    }
                    run = S;
                }
            }
            __syncthreads();
            int byte = s_byte;
            needed   = s_needed;
            for (int i = tid; i < nA; i += 1024) {
                u64 k = src[i];
                if ((int)((k >> shift) & 255) == byte)
                    dst[atomicAdd(&s_cnt, 1)] = k;
            }
            __syncthreads();
            nA = s_cnt;
            u64* t = src; src = dst; dst = t;
            __syncthreads();   // protect s_cnt/hist reset next level
        }
        u64 T = src[0];        // unique boundary key

        // winners: rescan global keys, key >= T  (W <= 400)
        if (tid == 0) s_cnt = 0;
        __syncthreads();
        for (int i = tid; i < BPB; i += 1024) {
            u64 key = g_key[b*BPB + i];
            if (key >= T) swin[atomicAdd(&s_cnt, 1)] = key;
        }
        __syncthreads();
        W = s_cnt;
    } else {
        // all candidates are winners (<=400 boxes)
        for (int i = tid; i < nA; i += 1024) swin[i] = A[i];
        __syncthreads();
        W = nA;
    }

    // ---- rank (O(W^2), W<=400) + expand ----
    bool areaOrder = (total > MAXQ);
    for (int w = tid; w < W; w += 1024) {
        u64 key = swin[w];
        unsigned inv = (unsigned)((key >> 6) & 0x3FFFull);
        int off = 0;
        for (int v = 0; v < W; v++) {
            u64 kv = swin[v];
            bool earlier = areaOrder
                ? (kv > key)                                   // area desc, idx asc
                : (((unsigned)((kv >> 6) & 0x3FFFull)) > inv); // idx asc
            if (earlier) off += (int)(kv & 63ull);
        }
        int boxLocal = 0x3FFF - (int)inv;
        u64 bm = g_bitmap[b*BPB + boxLocal];
        int cnt  = (int)(key & 63ull);
        int take = min(cnt, MAXQ - off);
        for (int t = 0; t < take; t++) {
            int d = __ffsll((long long)bm) - 1;   // depths asc = flat index asc
            bm &= bm - 1;
            ssel[off + t] = (boxLocal << 6) | d;
        }
    }
    __syncthreads();

    // ---- output ----
    if (tid < MAXQ) {
        const float DENOM = (float)(102.400001);
        float rx, ry, rz, pm;
        if (tid < filled) {
            int v = ssel[tid];
            int boxLocal = v >> 6;
            int dd = v & 63;
            int box_gid = b*BPB + boxLocal;
            int c = boxLocal / NBOX;
            int cam = b*NCAM + c;
            float4 bx = ((const float4*)boxes)[box_gid];
            CamData cd; load_cam(Kmat, Emat, cam, cd);
            cd.cx = (bx.x + bx.z)*0.5f;
            cd.cy = (bx.y + bx.w)*0.5f;
            float d = depth_of(dd);
            float X,Y,Z; fwd_point(cd, d, X, Y, Z);
            rx = fminf(fmaxf((X + 51.2f)/DENOM, 0.0f), 1.0f);
            ry = fminf(fmaxf((Y + 51.2f)/DENOM, 0.0f), 1.0f);
            rz = fminf(fmaxf((Z + 51.2f)/DENOM, 0.0f), 1.0f);
            pm = 0.0f;
        } else {
            float pad = fminf(fmaxf(51.2f/DENOM, 0.0f), 1.0f);  // sel=0 path
            rx = ry = rz = pad;
            pm = 1.0f;
        }
        int rbase = (b*MAXQ + tid)*3;
        out[rbase + 0] = rx;
        out[rbase + 1] = ry;
        out[rbase + 2] = rz;
        if (out_size >= NB*MAXQ*4)
            out[NB*MAXQ*3 + b*MAXQ + tid] = pm;
    }
}

// ---------------------------------------------------------------------------
extern "C" void kernel_launch(void* const* d_in, const int* in_sizes, int n_in,
                              void* d_out, int out_size)
{
    const float* boxes = (const float*)d_in[0];   // (8,6,900,4)
    const float* Kmat  = (const float*)d_in[1];   // (8,6,4,4)
    const float* Emat  = (const float*)d_in[2];   // (8,6,4,4)
    float* out = (float*)d_out;

    const int smem_bytes = 2*BPB*8 + MAXQ*8 + MAXQ*4;   // 91200 B
    cudaFuncSetAttribute(k_select, cudaFuncAttributeMaxDynamicSharedMemorySize,
                         smem_bytes);

    k_mask<<<(TOTAL_BOXES*8)/256, 256>>>(boxes, Kmat, Emat);
    k_select<<<NB, 1024, smem_bytes>>>(boxes, Kmat, Emat, out, out_size);
}

// round 4
// speedup vs baseline: 5.0069x; 1.0125x over previous
#include <cuda_runtime.h>
#include <stdint.h>

#define NB   8
#define NCAM 6
#define NBOX 900
#define ND   48
#define BPB  (NCAM*NBOX)            /* 5400  */
#define TOTAL_BOXES (NB*BPB)        /* 43200 */
#define MAXQ 400
#define ITERS1 6                    /* ceil(5400/1024) */

typedef unsigned long long u64;

// Scratch (fully overwritten every call -> deterministic, graph-safe)
__device__ u64 g_bitmap[TOTAL_BOXES];
__device__ u64 g_key[TOTAL_BOXES];

struct CamData {
    float f, kf, k02, k12;
    float e00,e01,e02,e03, e10,e11,e12,e13, e20,e21,e22,e23;
    float cx, cy;
};

__device__ __forceinline__ float depth_of(int dd) {
    const float step = 59.0f / 47.0f;
    if (dd == ND-1) return 60.0f;                // linspace endpoint exact
    return __fadd_rn(__fmul_rn((float)dd, step), 1.0f);
}

__device__ __forceinline__ void load_cam(const float* __restrict__ Kmat,
                                         const float* __restrict__ Emat,
                                         int cam, CamData& cd) {
    float f = Kmat[cam*16 + 0];
    cd.f   = f;
    cd.kf  = 1.0f / f;
    cd.k02 = -(400.0f * cd.kf);
    cd.k12 = -(224.0f * cd.kf);
    const float* e = Emat + cam*16;
    cd.e00=e[0];  cd.e01=e[1];  cd.e02=e[2];  cd.e03=e[3];
    cd.e10=e[4];  cd.e11=e[5];  cd.e12=e[6];  cd.e13=e[7];
    cd.e20=e[8];  cd.e21=e[9];  cd.e22=e[10]; cd.e23=e[11];
}

__device__ __forceinline__ void fwd_point(const CamData& cd, float d,
                                          float& X, float& Y, float& Z) {
    float pcx = cd.kf*(cd.cx*d) + cd.k02*d;
    float pcy = cd.kf*(cd.cy*d) + cd.k12*d;
    X = cd.e00*pcx + cd.e01*pcy + cd.e02*d + cd.e03;
    Y = cd.e10*pcx + cd.e11*pcy + cd.e12*d + cd.e13;
    Z = cd.e20*pcx + cd.e21*pcy + cd.e22*d + cd.e23;
}

// warp-aggregated compaction slot (uniform loops only; full-warp ballot)
__device__ __forceinline__ int ballot_slot(bool pred, int* counter) {
    unsigned m = __ballot_sync(0xffffffffu, pred);
    if (!m) return -1;
    int lane = threadIdx.x & 31;
    int rank = __popc(m & ((1u << lane) - 1));
    int leader = __ffs(m) - 1;
    int base = 0;
    if (lane == leader) base = atomicAdd(counter, __popc(m));
    base = __shfl_sync(0xffffffffu, base, leader);
    return base + rank;
}

// warp 0: merge 4 hist replicas, suffix-sum, pick boundary bucket
__device__ __forceinline__ void pick_bucket(const int* hist4, int needed,
                                            int tid, int* s_byte, int* s_needed) {
    if (tid < 32) {
        int s[8]; int lt = 0;
        #pragma unroll
        for (int j = 0; j < 8; j++) {
            int bin = tid*8 + j;
            int v = hist4[bin] + hist4[256+bin] + hist4[512+bin] + hist4[768+bin];
            s[j] = v; lt += v;
        }
        int suf = lt;
        #pragma unroll
        for (int off = 1; off < 32; off <<= 1) {
            int v = __shfl_down_sync(0xffffffffu, suf, off);
            if (tid + off < 32) suf += v;
        }
        int run = suf - lt;                // sum over lanes > tid
        #pragma unroll
        for (int j = 7; j >= 0; j--) {
            int S = run + s[j];
            if (S >= needed && run < needed) { *s_byte = tid*8 + j; *s_needed = needed - run; }
            run = S;
        }
    }
}

// ---------------------------------------------------------------------------
// K1: per-box mask bitmap + composite key. 8 lanes/box, 6 depths/lane.
// key64 = areaBits<<32 | (0x3FFF - boxIdx)<<6 | cnt   (larger = better, unique)
// ---------------------------------------------------------------------------
__global__ void __launch_bounds__(256)
k_mask(const float* __restrict__ boxes,
       const float* __restrict__ Kmat,
       const float* __restrict__ Emat)
{
    int tid = blockIdx.x * blockDim.x + threadIdx.x;
    int box_gid = tid >> 3;
    int chunk   = tid & 7;
    if (box_gid >= TOTAL_BOXES) return;

    int b  = box_gid / BPB;
    int bl = box_gid % BPB;
    int c  = bl / NBOX;
    int cam = b*NCAM + c;

    float4 bx = ((const float4*)boxes)[box_gid];
    CamData cd; load_cam(Kmat, Emat, cam, cd);
    cd.cx = (bx.x + bx.z)*0.5f;
    cd.cy = (bx.y + bx.w)*0.5f;

    float area = (bx.z - bx.x)*(bx.w - bx.y);
    bool valid = (area > 5.0f) && (area < 197120.0f);

    // Einv (rigid): Rinv = R^T, tinv = -R^T t ; bottom row exact
    float i00=cd.e00, i01=cd.e10, i02=cd.e20;
    float i10=cd.e01, i11=cd.e11, i12=cd.e21;
    float i20=cd.e02, i21=cd.e12, i22=cd.e22;
    float t0=cd.e03, t1=cd.e13, t2=cd.e23;
    float ti0 = -(i00*t0 + i01*t1 + i02*t2);
    float ti1 = -(i10*t0 + i11*t1 + i12*t2);
    float ti2 = -(i20*t0 + i21*t1 + i22*t2);

    const float INV_ONE_EPS = 1.0f / (1.0f + 1e-6f);

    u64 bmp = 0ull;
    #pragma unroll
    for (int r = 0; r < 6; r++) {
        int dd = chunk*6 + r;
        float d = depth_of(dd);
        float X,Y,Z;
        fwd_point(cd, d, X, Y, Z);
        float p0 = i00*X + i01*Y + i02*Z + ti0;
        float p1 = i10*X + i11*Y + i12*Z + ti1;
        float p2 = i20*X + i21*Y + i22*Z + ti2;
        float pc0 = p0 * INV_ONE_EPS;
        float pc1 = p1 * INV_ONE_EPS;
        float pc2 = p2 * INV_ONE_EPS;
        float pih0 = cd.f*pc0 + 400.0f*pc2;
        float pih1 = cd.f*pc1 + 224.0f*pc2;
        float zd = pc2 + 1e-6f;
        float invzd = 1.0f / zd;
        float imgx = pih0 * invzd;
        float imgy = pih1 * invzd;
        float bs = fminf(fmaxf(40.0f * (10.0f * invzd), 8.0f), 200.0f);
        float half = bs * 0.5f;
        float px0 = imgx - half, py0 = imgy - half;
        float px1 = imgx + half, py1 = imgy + half;
        float xx1 = fmaxf(px0, bx.x);
        float yy1 = fmaxf(py0, bx.y);
        float xx2 = fminf(px1, bx.z);
        float yy2 = fminf(py1, bx.w);
        float inter = fmaxf(xx2-xx1, 0.0f) * fmaxf(yy2-yy1, 0.0f);
        float a1 = (px1-px0)*(py1-py0);
        float iou = inter / (a1 + area - inter + 1e-6f);   // exact: threshold-sensitive
        if ((iou > 0.05f) && valid) bmp |= (1ull << dd);
    }
    bmp |= __shfl_xor_sync(0xffffffffu, bmp, 1);
    bmp |= __shfl_xor_sync(0xffffffffu, bmp, 2);
    bmp |= __shfl_xor_sync(0xffffffffu, bmp, 4);
    if (chunk == 0) {
        g_bitmap[box_gid] = bmp;
        int cnt = __popcll(bmp);
        u64 key = 0;
        if (cnt)
            key = ((u64)__float_as_uint(area) << 32)
                | ((u64)(0x3FFFu - (unsigned)bl) << 6)
                | (unsigned)cnt;
        g_key[box_gid] = key;
    }
}

// ---------------------------------------------------------------------------
// K2: per-batch selection. Single global pass (register-cached keys) builds
// the level-7 histogram + total; boundary bucket compacted in shared; levels
// 6..0 on the tiny bucket. All compactions warp-aggregated.
// ---------------------------------------------------------------------------
__global__ void __launch_bounds__(1024)
k_select(const float* __restrict__ boxes,
         const float* __restrict__ Kmat,
         const float* __restrict__ Emat,
         float* __restrict__ out, int out_size)
{
    extern __shared__ unsigned char sm[];
    u64* A    = (u64*)sm;                         // boundary bucket (<= 5400)
    u64* Bb   = A + BPB;                          // ping-pong
    u64* swin = Bb + BPB;                         // 400 winners
    int* ssel = (int*)(swin + MAXQ);              // 400 selections
    __shared__ int hist[1024];                    // 4 replicas x 256 bins
    __shared__ int s_cnt, s_total, s_byte, s_needed;

    int b    = blockIdx.x;
    int tid  = threadIdx.x;
    int repl = ((tid >> 5) & 3) << 8;             // histogram replica base
    if (tid == 0) { s_cnt = 0; s_total = 0; }
    hist[tid] = 0;
    __syncthreads();

    // ---- pass 1: read keys once (cache in regs), total + level-7 histogram
    u64 kloc[ITERS1];
    int my = 0;
    #pragma unroll
    for (int it = 0; it < ITERS1; it++) {
        int i = it*1024 + tid;
        u64 key = (i < BPB) ? g_key[b*BPB + i] : 0;
        kloc[it] = key;
        if (key) {
            my += (int)(key & 63ull);
            atomicAdd(&hist[repl + (int)(key >> 56)], (int)(key & 63ull));
        }
    }
    #pragma unroll
    for (int off = 16; off > 0; off >>= 1)
        my += __shfl_down_sync(0xffffffffu, my, off);
    if ((tid & 31) == 0 && my) atomicAdd(&s_total, my);
    __syncthreads();
    int total  = s_total;
    int filled = min(total, MAXQ);
    int W      = 0;

    if (total > MAXQ) {
        // ---- pick level-7 bucket, compact it into A ----
        pick_bucket(hist, MAXQ, tid, &s_byte, &s_needed);
        __syncthreads();
        int byte   = s_byte;
        int needed = s_needed;
        #pragma unroll
        for (int it = 0; it < ITERS1; it++) {
            u64 key = kloc[it];
            bool p = key && ((int)(key >> 56) == byte);
            int slot = ballot_slot(p, &s_cnt);
            if (p) A[slot] = key;
        }
        __syncthreads();
        int nA = s_cnt;

        // ---- levels 6..0 on the bucket (keys unique -> exit at nA==1) ----
        u64 *src = A, *dst = Bb;
        for (int level = 6; level >= 0 && nA > 1; --level) {
            int shift = level * 8;
            hist[tid] = 0;
            if (tid == 0) s_cnt = 0;
            __syncthreads();
            int iters = (nA + 1023) >> 10;
            for (int it = 0; it < iters; it++) {
                int i = it*1024 + tid;
                if (i < nA)
                    atomicAdd(&hist[repl + (int)((src[i] >> shift) & 255)],
                              (int)(src[i] & 63ull));
            }
            __syncthreads();
            pick_bucket(hist, needed, tid, &s_byte, &s_needed);
            __syncthreads();
            byte   = s_byte;
            needed = s_needed;
            for (int it = 0; it < iters; it++) {
                int i = it*1024 + tid;
                bool p = (i < nA) && ((int)((src[i] >> shift) & 255) == byte);
                u64 k = p ? src[i] : 0;
                int slot = ballot_slot(p, &s_cnt);
                if (p) dst[slot] = k;
            }
            __syncthreads();
            nA = s_cnt;
            u64* t = src; src = dst; dst = t;
            __syncthreads();
        }
        u64 T = src[0];                     // exact boundary key (unique)

        // ---- winners: key >= T from cached keys (W <= 400) ----
        if (tid == 0) s_cnt = 0;
        __syncthreads();
        #pragma unroll
        for (int it = 0; it < ITERS1; it++) {
            u64 key = kloc[it];
            bool p = (key >= T);            // T>0 excludes zero keys
            int slot = ballot_slot(p, &s_cnt);
            if (p) swin[slot] = key;
        }
        __syncthreads();
        W = s_cnt;
    } else {
        // all candidates are winners (#keys <= total <= 400)
        if (tid == 0) s_cnt = 0;
        __syncthreads();
        #pragma unroll
        for (int it = 0; it < ITERS1; it++) {
            u64 key = kloc[it];
            bool p = (key != 0);
            int slot = ballot_slot(p, &s_cnt);
            if (p) swin[slot] = key;
        }
        __syncthreads();
        W = s_cnt;
    }

    // ---- rank (O(W^2), W<=400) + expand ----
    bool areaOrder = (total > MAXQ);
    for (int w = tid; w < W; w += 1024) {
        u64 key = swin[w];
        unsigned inv = (unsigned)((key >> 6) & 0x3FFFull);
        int off = 0;
        for (int v = 0; v < W; v++) {
            u64 kv = swin[v];
            bool earlier = areaOrder
                ? (kv > key)                                   // area desc, idx asc
                : (((unsigned)((kv >> 6) & 0x3FFFull)) > inv); // idx asc
            if (earlier) off += (int)(kv & 63ull);
        }
        int boxLocal = 0x3FFF - (int)inv;
        u64 bm = g_bitmap[b*BPB + boxLocal];
        int cnt  = (int)(key & 63ull);
        int take = min(cnt, MAXQ - off);
        for (int t = 0; t < take; t++) {
            int d = __ffsll((long long)bm) - 1;   // depths asc = flat index asc
            bm &= bm - 1;
            ssel[off + t] = (boxLocal << 6) | d;
        }
    }
    __syncthreads();

    // ---- output ----
    if (tid < MAXQ) {
        const float DENOM = (float)(102.400001);
        float rx, ry, rz, pm;
        if (tid < filled) {
            int v = ssel[tid];
            int boxLocal = v >> 6;
            int dd = v & 63;
            int box_gid = b*BPB + boxLocal;
            int c = boxLocal / NBOX;
            int cam = b*NCAM + c;
            float4 bx = ((const float4*)boxes)[box_gid];
            CamData cd; load_cam(Kmat, Emat, cam, cd);
            cd.cx = (bx.x + bx.z)*0.5f;
            cd.cy = (bx.y + bx.w)*0.5f;
            float d = depth_of(dd);
            float X,Y,Z; fwd_point(cd, d, X, Y, Z);
            rx = fminf(fmaxf((X + 51.2f)/DENOM, 0.0f), 1.0f);
            ry = fminf(fmaxf((Y + 51.2f)/DENOM, 0.0f), 1.0f);
            rz = fminf(fmaxf((Z + 51.2f)/DENOM, 0.0f), 1.0f);
            pm = 0.0f;
        } else {
            float pad = fminf(fmaxf(51.2f/DENOM, 0.0f), 1.0f);
            rx = ry = rz = pad;
            pm = 1.0f;
        }
        int rbase = (b*MAXQ + tid)*3;
        out[rbase + 0] = rx;
        out[rbase + 1] = ry;
        out[rbase + 2] = rz;
        if (out_size >= NB*MAXQ*4)
            out[NB*MAXQ*3 + b*MAXQ + tid] = pm;
    }
}

// ---------------------------------------------------------------------------
extern "C" void kernel_launch(void* const* d_in, const int* in_sizes, int n_in,
                              void* d_out, int out_size)
{
    const float* boxes = (const float*)d_in[0];   // (8,6,900,4)
    const float* Kmat  = (const float*)d_in[1];   // (8,6,4,4)
    const float* Emat  = (const float*)d_in[2];   // (8,6,4,4)
    float* out = (float*)d_out;

    const int smem_bytes = 2*BPB*8 + MAXQ*8 + MAXQ*4;   // 91200 B
    cudaFuncSetAttribute(k_select, cudaFuncAttributeMaxDynamicSharedMemorySize,
                         smem_bytes);

    k_mask<<<(TOTAL_BOXES*8)/256, 256>>>(boxes, Kmat, Emat);
    k_select<<<NB, 1024, smem_bytes>>>(boxes, Kmat, Emat, out, out_size);
}

// round 5
// speedup vs baseline: 5.4374x; 1.0860x over previous
#include <cuda_runtime.h>
#include <stdint.h>

#define NB   8
#define NCAM 6
#define NBOX 900
#define ND   48
#define BPB  (NCAM*NBOX)            /* 5400  */
#define TOTAL_BOXES (NB*BPB)        /* 43200 */
#define MAXQ 400
#define ITERS1 6                    /* ceil(5400/1024) */
#define NBIN 4096

typedef unsigned long long u64;

// Scratch (fully overwritten every call -> deterministic, graph-safe)
__device__ u64 g_bitmap[TOTAL_BOXES];
__device__ u64 g_key[TOTAL_BOXES];

struct CamData {
    float f, kf, k02, k12;
    float e00,e01,e02,e03, e10,e11,e12,e13, e20,e21,e22,e23;
    float cx, cy;
};

__device__ __forceinline__ float depth_of(int dd) {
    const float step = 59.0f / 47.0f;
    if (dd == ND-1) return 60.0f;                // linspace endpoint exact
    return __fadd_rn(__fmul_rn((float)dd, step), 1.0f);
}

__device__ __forceinline__ void load_cam(const float* __restrict__ Kmat,
                                         const float* __restrict__ Emat,
                                         int cam, CamData& cd) {
    float f = Kmat[cam*16 + 0];
    cd.f   = f;
    cd.kf  = 1.0f / f;
    cd.k02 = -(400.0f * cd.kf);
    cd.k12 = -(224.0f * cd.kf);
    const float* e = Emat + cam*16;
    cd.e00=e[0];  cd.e01=e[1];  cd.e02=e[2];  cd.e03=e[3];
    cd.e10=e[4];  cd.e11=e[5];  cd.e12=e[6];  cd.e13=e[7];
    cd.e20=e[8];  cd.e21=e[9];  cd.e22=e[10]; cd.e23=e[11];
}

__device__ __forceinline__ void fwd_point(const CamData& cd, float d,
                                          float& X, float& Y, float& Z) {
    float pcx = cd.kf*(cd.cx*d) + cd.k02*d;
    float pcy = cd.kf*(cd.cy*d) + cd.k12*d;
    X = cd.e00*pcx + cd.e01*pcy + cd.e02*d + cd.e03;
    Y = cd.e10*pcx + cd.e11*pcy + cd.e12*d + cd.e13;
    Z = cd.e20*pcx + cd.e21*pcy + cd.e22*d + cd.e23;
}

// warp-aggregated compaction slot (call with ALL 32 lanes converged)
__device__ __forceinline__ int ballot_slot(bool pred, int* counter) {
    unsigned m = __ballot_sync(0xffffffffu, pred);
    if (!m) return -1;
    int lane = threadIdx.x & 31;
    int rank = __popc(m & ((1u << lane) - 1));
    int leader = __ffs(m) - 1;
    int base = 0;
    if (lane == leader) base = atomicAdd(counter, __popc(m));
    base = __shfl_sync(0xffffffffu, base, leader);
    return base + rank;
}

// ---------------------------------------------------------------------------
// K1: per-box mask bitmap + composite key. 8 lanes/box, 6 depths/lane.
// key64 = areaBits<<32 | (0x3FFF - boxIdx)<<6 | cnt   (larger = better, unique)
// ---------------------------------------------------------------------------
__global__ void __launch_bounds__(256)
k_mask(const float* __restrict__ boxes,
       const float* __restrict__ Kmat,
       const float* __restrict__ Emat)
{
    int tid = blockIdx.x * blockDim.x + threadIdx.x;
    int box_gid = tid >> 3;
    int chunk   = tid & 7;
    if (box_gid >= TOTAL_BOXES) return;

    int b  = box_gid / BPB;
    int bl = box_gid % BPB;
    int c  = bl / NBOX;
    int cam = b*NCAM + c;

    float4 bx = ((const float4*)boxes)[box_gid];
    CamData cd; load_cam(Kmat, Emat, cam, cd);
    cd.cx = (bx.x + bx.z)*0.5f;
    cd.cy = (bx.y + bx.w)*0.5f;

    float area = (bx.z - bx.x)*(bx.w - bx.y);
    bool valid = (area > 5.0f) && (area < 197120.0f);

    // Einv (rigid): Rinv = R^T, tinv = -R^T t ; bottom row exact
    float i00=cd.e00, i01=cd.e10, i02=cd.e20;
    float i10=cd.e01, i11=cd.e11, i12=cd.e21;
    float i20=cd.e02, i21=cd.e12, i22=cd.e22;
    float t0=cd.e03, t1=cd.e13, t2=cd.e23;
    float ti0 = -(i00*t0 + i01*t1 + i02*t2);
    float ti1 = -(i10*t0 + i11*t1 + i12*t2);
    float ti2 = -(i20*t0 + i21*t1 + i22*t2);

    const float INV_ONE_EPS = 1.0f / (1.0f + 1e-6f);

    u64 bmp = 0ull;
    #pragma unroll
    for (int r = 0; r < 6; r++) {
        int dd = chunk*6 + r;
        float d = depth_of(dd);
        float X,Y,Z;
        fwd_point(cd, d, X, Y, Z);
        float p0 = i00*X + i01*Y + i02*Z + ti0;
        float p1 = i10*X + i11*Y + i12*Z + ti1;
        float p2 = i20*X + i21*Y + i22*Z + ti2;
        float pc0 = p0 * INV_ONE_EPS;
        float pc1 = p1 * INV_ONE_EPS;
        float pc2 = p2 * INV_ONE_EPS;
        float pih0 = cd.f*pc0 + 400.0f*pc2;
        float pih1 = cd.f*pc1 + 224.0f*pc2;
        float zd = pc2 + 1e-6f;
        float invzd = 1.0f / zd;
        float imgx = pih0 * invzd;
        float imgy = pih1 * invzd;
        float bs = fminf(fmaxf(40.0f * (10.0f * invzd), 8.0f), 200.0f);
        float half = bs * 0.5f;
        float px0 = imgx - half, py0 = imgy - half;
        float px1 = imgx + half, py1 = imgy + half;
        float xx1 = fmaxf(px0, bx.x);
        float yy1 = fmaxf(py0, bx.y);
        float xx2 = fminf(px1, bx.z);
        float yy2 = fminf(py1, bx.w);
        float inter = fmaxf(xx2-xx1, 0.0f) * fmaxf(yy2-yy1, 0.0f);
        float a1 = (px1-px0)*(py1-py0);
        float iou = inter / (a1 + area - inter + 1e-6f);   // exact: threshold-sensitive
        if ((iou > 0.05f) && valid) bmp |= (1ull << dd);
    }
    bmp |= __shfl_xor_sync(0xffffffffu, bmp, 1);
    bmp |= __shfl_xor_sync(0xffffffffu, bmp, 2);
    bmp |= __shfl_xor_sync(0xffffffffu, bmp, 4);
    if (chunk == 0) {
        g_bitmap[box_gid] = bmp;
        int cnt = __popcll(bmp);
        u64 key = 0;
        if (cnt)
            key = ((u64)__float_as_uint(area) << 32)
                | ((u64)(0x3FFFu - (unsigned)bl) << 6)
                | (unsigned)cnt;
        g_key[box_gid] = key;
    }
}

// ---------------------------------------------------------------------------
// K2: per-batch selection. One weighted 4096-bin histogram on the top 12 key
// bits + one block suffix-scan finds the boundary bin; exact boundary key T
// resolved inside the (small) bin; then winners, 2-way-split rank, expand.
// ---------------------------------------------------------------------------
__global__ void __launch_bounds__(1024)
k_select(const float* __restrict__ boxes,
         const float* __restrict__ Kmat,
         const float* __restrict__ Emat,
         float* __restrict__ out, int out_size)
{
    extern __shared__ u64 A[];                    // boundary-bin keys (<= 5400)
    __shared__ int hist[NBIN];                    // 16 KB
    __shared__ u64 swin[MAXQ];
    __shared__ int ssel[MAXQ];
    __shared__ int wsum[32], wrun[32];
    __shared__ int s_cnt, s_total, s_bin, s_needed;
    __shared__ u64 s_T;

    int b    = blockIdx.x;
    int tid  = threadIdx.x;
    int lane = tid & 31;
    int wid  = tid >> 5;
    if (tid == 0) { s_cnt = 0; s_total = 0; }
    #pragma unroll
    for (int j = 0; j < NBIN/1024; j++) hist[j*1024 + tid] = 0;
    __syncthreads();

    // ---- single pass: read keys (cache in regs), total + 4096-bin hist ----
    u64 kloc[ITERS1];
    int my = 0;
    #pragma unroll
    for (int it = 0; it < ITERS1; it++) {
        int i = it*1024 + tid;
        u64 key = (i < BPB) ? g_key[b*BPB + i] : 0;
        kloc[it] = key;
        if (key) {
            my += (int)(key & 63ull);
            atomicAdd(&hist[(int)(key >> 52)], (int)(key & 63ull));
        }
    }
    #pragma unroll
    for (int off = 16; off > 0; off >>= 1)
        my += __shfl_down_sync(0xffffffffu, my, off);
    if (lane == 0 && my) atomicAdd(&s_total, my);
    __syncthreads();
    int total  = s_total;
    int filled = min(total, MAXQ);
    int W      = 0;

    if (total > MAXQ) {
        // ---- block suffix-scan over 4096 bins, find boundary bin ----
        int base_bin = tid * 4;
        int h0 = hist[base_bin+0], h1 = hist[base_bin+1];
        int h2 = hist[base_bin+2], h3 = hist[base_bin+3];
        int ls = h0 + h1 + h2 + h3;
        int suf = ls;
        #pragma unroll
        for (int off = 1; off < 32; off <<= 1) {
            int v = __shfl_down_sync(0xffffffffu, suf, off);
            if (lane + off < 32) suf += v;
        }
        int run = suf - ls;                       // lanes > lane, this warp
        if (lane == 0) wsum[wid] = suf;
        __syncthreads();
        if (tid < 32) {
            int wv = wsum[tid];
            int ws = wv;
            #pragma unroll
            for (int off = 1; off < 32; off <<= 1) {
                int v = __shfl_down_sync(0xffffffffu, ws, off);
                if (tid + off < 32) ws += v;
            }
            wrun[tid] = ws - wv;                  // warps > tid
        }
        __syncthreads();
        int r = wrun[wid] + run;                  // weight strictly above my 4 bins
        // walk bins high -> low (exactly one thread hits the boundary)
        if (r < MAXQ && r + h3 >= MAXQ) { s_bin = base_bin+3; s_needed = MAXQ - r; }
        r += h3;
        if (r < MAXQ && r + h2 >= MAXQ) { s_bin = base_bin+2; s_needed = MAXQ - r; }
        r += h2;
        if (r < MAXQ && r + h1 >= MAXQ) { s_bin = base_bin+1; s_needed = MAXQ - r; }
        r += h1;
        if (r < MAXQ && r + h0 >= MAXQ) { s_bin = base_bin+0; s_needed = MAXQ - r; }
        __syncthreads();
        int bin    = s_bin;
        int needed = s_needed;

        // ---- compact boundary-bin keys into A ----
        #pragma unroll
        for (int it = 0; it < ITERS1; it++) {
            u64 key = kloc[it];
            bool p = key && ((int)(key >> 52) == bin);
            int slot = ballot_slot(p, &s_cnt);
            if (p) A[slot] = key;
        }
        __syncthreads();
        int nA = s_cnt;

        // ---- exact boundary key T inside the bin (nA small) ----
        for (int w = tid; w < nA; w += 1024) {
            u64 k = A[w];
            int off = 0;
            for (int v = 0; v < nA; v++) {
                u64 kv = A[v];
                if (kv > k) off += (int)(kv & 63ull);
            }
            int wt = (int)(k & 63ull);
            if (off < needed && needed <= off + wt) s_T = k;   // unique writer
        }
        __syncthreads();
        u64 T = s_T;

        // ---- winners: key >= T (W <= 400 boxes) ----
        if (tid == 0) s_cnt = 0;
        __syncthreads();
        #pragma unroll
        for (int it = 0; it < ITERS1; it++) {
            u64 key = kloc[it];
            bool p = (key >= T);                  // T>0 excludes zero keys
            int slot = ballot_slot(p, &s_cnt);
            if (p) swin[slot] = key;
        }
        __syncthreads();
        W = s_cnt;
    } else {
        if (tid == 0) s_cnt = 0;
        __syncthreads();
        #pragma unroll
        for (int it = 0; it < ITERS1; it++) {
            u64 key = kloc[it];
            bool p = (key != 0);
            int slot = ballot_slot(p, &s_cnt);
            if (p) swin[slot] = key;
        }
        __syncthreads();
        W = s_cnt;
    }

    // ---- rank (2 threads per winner) + expand ----
    if (W > 0) {
        bool areaOrder = (total > MAXQ);
        bool validw = (tid < 2*W);
        int w   = validw ? (tid >> 1) : 0;
        int par = tid & 1;
        u64 key = swin[w];
        unsigned inv = (unsigned)((key >> 6) & 0x3FFFull);
        int part = 0;
        for (int v = par; v < W; v += 2) {
            u64 kv = swin[v];
            bool earlier = areaOrder
                ? (kv > key)
                : (((unsigned)((kv >> 6) & 0x3FFFull)) > inv);
            if (earlier) part += (int)(kv & 63ull);
        }
        int off = part + __shfl_xor_sync(0xffffffffu, part, 1);
        if (validw && par == 0) {
            int boxLocal = 0x3FFF - (int)inv;
            u64 bm = g_bitmap[b*BPB + boxLocal];
            int cnt  = (int)(key & 63ull);
            int take = min(cnt, MAXQ - off);
            for (int t = 0; t < take; t++) {
                int d = __ffsll((long long)bm) - 1;
                bm &= bm - 1;
                ssel[off + t] = (boxLocal << 6) | d;
            }
        }
    }
    __syncthreads();

    // ---- output ----
    if (tid < MAXQ) {
        const float DENOM = (float)(102.400001);
        float rx, ry, rz, pm;
        if (tid < filled) {
            int v = ssel[tid];
            int boxLocal = v >> 6;
            int dd = v & 63;
            int box_gid = b*BPB + boxLocal;
            int c = boxLocal / NBOX;
            int cam = b*NCAM + c;
            float4 bx = ((const float4*)boxes)[box_gid];
            CamData cd; load_cam(Kmat, Emat, cam, cd);
            cd.cx = (bx.x + bx.z)*0.5f;
            cd.cy = (bx.y + bx.w)*0.5f;
            float d = depth_of(dd);
            float X,Y,Z; fwd_point(cd, d, X, Y, Z);
            rx = fminf(fmaxf((X + 51.2f)/DENOM, 0.0f), 1.0f);
            ry = fminf(fmaxf((Y + 51.2f)/DENOM, 0.0f), 1.0f);
            rz = fminf(fmaxf((Z + 51.2f)/DENOM, 0.0f), 1.0f);
            pm = 0.0f;
        } else {
            float pad = fminf(fmaxf(51.2f/DENOM, 0.0f), 1.0f);
            rx = ry = rz = pad;
            pm = 1.0f;
        }
        int rbase = (b*MAXQ + tid)*3;
        out[rbase + 0] = rx;
        out[rbase + 1] = ry;
        out[rbase + 2] = rz;
        if (out_size >= NB*MAXQ*4)
            out[NB*MAXQ*3 + b*MAXQ + tid] = pm;
    }
}

// ---------------------------------------------------------------------------
extern "C" void kernel_launch(void* const* d_in, const int* in_sizes, int n_in,
                              void* d_out, int out_size)
{
    const float* boxes = (const float*)d_in[0];   // (8,6,900,4)
    const float* Kmat  = (const float*)d_in[1];   // (8,6,4,4)
    const float* Emat  = (const float*)d_in[2];   // (8,6,4,4)
    float* out = (float*)d_out;

    const int smem_bytes = BPB * 8;               // 43200 B (A only)
    cudaFuncSetAttribute(k_select, cudaFuncAttributeMaxDynamicSharedMemorySize,
                         smem_bytes);

    k_mask<<<(TOTAL_BOXES*8)/256, 256>>>(boxes, Kmat, Emat);
    k_select<<<NB, 1024, smem_bytes>>>(boxes, Kmat, Emat, out, out_size);
}

// round 6
// speedup vs baseline: 6.0588x; 1.1143x over previous
#include <cuda_runtime.h>
#include <stdint.h>

#define NB   8
#define NCAM 6
#define NBOX 900
#define ND   48
#define BPB  (NCAM*NBOX)            /* 5400  */
#define TOTAL_BOXES (NB*BPB)        /* 43200 */
#define MAXQ 400
#define ITERS1 6                    /* ceil(5400/1024) */
#define NBIN 4096

typedef unsigned long long u64;

// Scratch (fully overwritten every call -> deterministic, graph-safe)
__device__ u64 g_bitmap[TOTAL_BOXES];
__device__ u64 g_key[TOTAL_BOXES];

struct CamData {
    float f, kf, k02, k12;
    float e00,e01,e02,e03, e10,e11,e12,e13, e20,e21,e22,e23;
    float cx, cy;
};

__device__ __forceinline__ float depth_of(int dd) {
    const float step = 59.0f / 47.0f;
    if (dd == ND-1) return 60.0f;                // linspace endpoint exact
    return __fadd_rn(__fmul_rn((float)dd, step), 1.0f);
}

__device__ __forceinline__ void load_cam(const float* __restrict__ Kmat,
                                         const float* __restrict__ Emat,
                                         int cam, CamData& cd) {
    float f = Kmat[cam*16 + 0];
    cd.f   = f;
    cd.kf  = 1.0f / f;
    cd.k02 = -(400.0f * cd.kf);
    cd.k12 = -(224.0f * cd.kf);
    const float* e = Emat + cam*16;
    cd.e00=e[0];  cd.e01=e[1];  cd.e02=e[2];  cd.e03=e[3];
    cd.e10=e[4];  cd.e11=e[5];  cd.e12=e[6];  cd.e13=e[7];
    cd.e20=e[8];  cd.e21=e[9];  cd.e22=e[10]; cd.e23=e[11];
}

__device__ __forceinline__ void fwd_point(const CamData& cd, float d,
                                          float& X, float& Y, float& Z) {
    float pcx = cd.kf*(cd.cx*d) + cd.k02*d;
    float pcy = cd.kf*(cd.cy*d) + cd.k12*d;
    X = cd.e00*pcx + cd.e01*pcy + cd.e02*d + cd.e03;
    Y = cd.e10*pcx + cd.e11*pcy + cd.e12*d + cd.e13;
    Z = cd.e20*pcx + cd.e21*pcy + cd.e22*d + cd.e23;
}

// warp-aggregated compaction slot (call with ALL 32 lanes converged)
__device__ __forceinline__ int ballot_slot(bool pred, int* counter) {
    unsigned m = __ballot_sync(0xffffffffu, pred);
    if (!m) return -1;
    int lane = threadIdx.x & 31;
    int rank = __popc(m & ((1u << lane) - 1));
    int leader = __ffs(m) - 1;
    int base = 0;
    if (lane == leader) base = atomicAdd(counter, __popc(m));
    base = __shfl_sync(0xffffffffu, base, leader);
    return base + rank;
}

// ---------------------------------------------------------------------------
// K1: per-box mask bitmap + composite key. 4 lanes/box, 12 depths/lane.
// key64 = areaBits<<32 | (0x3FFF - boxIdx)<<6 | cnt   (larger = better, unique)
// ---------------------------------------------------------------------------
__global__ void __launch_bounds__(256)
k_mask(const float* __restrict__ boxes,
       const float* __restrict__ Kmat,
       const float* __restrict__ Emat)
{
    int tid = blockIdx.x * blockDim.x + threadIdx.x;
    int box_gid = tid >> 2;
    int chunk   = tid & 3;
    if (box_gid >= TOTAL_BOXES) return;

    int b  = box_gid / BPB;
    int bl = box_gid % BPB;
    int c  = bl / NBOX;
    int cam = b*NCAM + c;

    float4 bx = ((const float4*)boxes)[box_gid];
    CamData cd; load_cam(Kmat, Emat, cam, cd);
    cd.cx = (bx.x + bx.z)*0.5f;
    cd.cy = (bx.y + bx.w)*0.5f;

    float area = (bx.z - bx.x)*(bx.w - bx.y);
    bool valid = (area > 5.0f) && (area < 197120.0f);

    // Einv (rigid): Rinv = R^T, tinv = -R^T t ; bottom row exact
    float i00=cd.e00, i01=cd.e10, i02=cd.e20;
    float i10=cd.e01, i11=cd.e11, i12=cd.e21;
    float i20=cd.e02, i21=cd.e12, i22=cd.e22;
    float t0=cd.e03, t1=cd.e13, t2=cd.e23;
    float ti0 = -(i00*t0 + i01*t1 + i02*t2);
    float ti1 = -(i10*t0 + i11*t1 + i12*t2);
    float ti2 = -(i20*t0 + i21*t1 + i22*t2);

    const float INV_ONE_EPS = 1.0f / (1.0f + 1e-6f);

    u64 bmp = 0ull;
    #pragma unroll
    for (int r = 0; r < 12; r++) {
        int dd = chunk*12 + r;
        float d = depth_of(dd);
        float X,Y,Z;
        fwd_point(cd, d, X, Y, Z);
        float p0 = i00*X + i01*Y + i02*Z + ti0;
        float p1 = i10*X + i11*Y + i12*Z + ti1;
        float p2 = i20*X + i21*Y + i22*Z + ti2;
        float pc0 = p0 * INV_ONE_EPS;
        float pc1 = p1 * INV_ONE_EPS;
        float pc2 = p2 * INV_ONE_EPS;
        float pih0 = cd.f*pc0 + 400.0f*pc2;
        float pih1 = cd.f*pc1 + 224.0f*pc2;
        float zd = pc2 + 1e-6f;
        float invzd = 1.0f / zd;
        float imgx = pih0 * invzd;
        float imgy = pih1 * invzd;
        float bs = fminf(fmaxf(40.0f * (10.0f * invzd), 8.0f), 200.0f);
        float half = bs * 0.5f;
        float px0 = imgx - half, py0 = imgy - half;
        float px1 = imgx + half, py1 = imgy + half;
        float xx1 = fmaxf(px0, bx.x);
        float yy1 = fmaxf(py0, bx.y);
        float xx2 = fminf(px1, bx.z);
        float yy2 = fminf(py1, bx.w);
        float inter = fmaxf(xx2-xx1, 0.0f) * fmaxf(yy2-yy1, 0.0f);
        float a1 = (px1-px0)*(py1-py0);
        float iou = inter / (a1 + area - inter + 1e-6f);   // exact: threshold-sensitive
        if ((iou > 0.05f) && valid) bmp |= (1ull << dd);
    }
    bmp |= __shfl_xor_sync(0xffffffffu, bmp, 1);
    bmp |= __shfl_xor_sync(0xffffffffu, bmp, 2);
    if (chunk == 0) {
        g_bitmap[box_gid] = bmp;
        int cnt = __popcll(bmp);
        u64 key = 0;
        if (cnt)
            key = ((u64)__float_as_uint(area) << 32)
                | ((u64)(0x3FFFu - (unsigned)bl) << 6)
                | (unsigned)cnt;
        g_key[box_gid] = key;
    }
}

// ---------------------------------------------------------------------------
// K2: per-batch selection, 5 phases:
//   P1 load keys + weighted 4096-bin histogram + total
//   P2 suffix-scan; hist[bin] := weighted sum of bins STRICTLY above (sufAbove)
//   P3 winners = keys with sufAbove[bin] < MAXQ (warp-aggregated compaction)
//   P4 off = sufAbove[bin] + same-bin weighted rank; expand if off < MAXQ
//   P5 output
// ---------------------------------------------------------------------------
__global__ void __launch_bounds__(1024)
k_select(const float* __restrict__ boxes,
         const float* __restrict__ Kmat,
         const float* __restrict__ Emat,
         float* __restrict__ out, int out_size)
{
    extern __shared__ u64 swin[];                 // winner keys (<= 5400)
    __shared__ int hist[NBIN];                    // 16 KB
    __shared__ int ssel[MAXQ];
    __shared__ int wsum[32], wrun[32];
    __shared__ int s_cnt, s_total;

    int b    = blockIdx.x;
    int tid  = threadIdx.x;
    int lane = tid & 31;
    int wid  = tid >> 5;
    if (tid == 0) { s_cnt = 0; s_total = 0; }
    #pragma unroll
    for (int j = 0; j < NBIN/1024; j++) hist[j*1024 + tid] = 0;
    __syncthreads();

    // ---- P1 ----
    u64 kloc[ITERS1];
    int my = 0;
    #pragma unroll
    for (int it = 0; it < ITERS1; it++) {
        int i = it*1024 + tid;
        u64 key = (i < BPB) ? g_key[b*BPB + i] : 0;
        kloc[it] = key;
        if (key) {
            my += (int)(key & 63ull);
            atomicAdd(&hist[(int)(key >> 52)], (int)(key & 63ull));
        }
    }
    #pragma unroll
    for (int off = 16; off > 0; off >>= 1)
        my += __shfl_down_sync(0xffffffffu, my, off);
    if (lane == 0 && my) atomicAdd(&s_total, my);
    __syncthreads();
    int total  = s_total;
    int filled = min(total, MAXQ);
    bool areaOrder = (total > MAXQ);

    // ---- P2: suffix scan -> hist becomes sufAbove (exclusive, from above) ----
    if (areaOrder) {
        int base_bin = tid * 4;
        int h0 = hist[base_bin+0], h1 = hist[base_bin+1];
        int h2 = hist[base_bin+2], h3 = hist[base_bin+3];
        int ls = h0 + h1 + h2 + h3;
        int suf = ls;
        #pragma unroll
        for (int off = 1; off < 32; off <<= 1) {
            int v = __shfl_down_sync(0xffffffffu, suf, off);
            if (lane + off < 32) suf += v;
        }
        int run = suf - ls;                       // lanes > lane, this warp
        if (lane == 0) wsum[wid] = suf;
        __syncthreads();
        if (tid < 32) {
            int wv = wsum[tid];
            int ws = wv;
            #pragma unroll
            for (int off = 1; off < 32; off <<= 1) {
                int v = __shfl_down_sync(0xffffffffu, ws, off);
                if (tid + off < 32) ws += v;
            }
            wrun[tid] = ws - wv;                  // warps > tid
        }
        __syncthreads();
        int r = wrun[wid] + run;                  // strictly above my 4 bins
        hist[base_bin+3] = r;
        hist[base_bin+2] = r + h3;
        hist[base_bin+1] = r + h3 + h2;
        hist[base_bin+0] = r + h3 + h2 + h1;
        __syncthreads();
    }

    // ---- P3: winner compaction ----
    #pragma unroll
    for (int it = 0; it < ITERS1; it++) {
        u64 key = kloc[it];
        bool p;
        if (areaOrder) p = key && (hist[(int)(key >> 52)] < MAXQ);
        else           p = (key != 0);
        int slot = ballot_slot(p, &s_cnt);
        if (p) swin[slot] = key;
    }
    __syncthreads();
    int W = s_cnt;

    // ---- P4: rank + expand ----
    for (int w = tid; w < W; w += 1024) {
        u64 key = swin[w];
        int off;
        if (areaOrder) {
            int myBin = (int)(key >> 52);
            off = hist[myBin];                    // sufAbove
            for (int v = 0; v < W; v++) {
                u64 kv = swin[v];
                if (kv > key && (int)(kv >> 52) == myBin)
                    off += (int)(kv & 63ull);
            }
        } else {
            unsigned inv = (unsigned)((key >> 6) & 0x3FFFull);
            off = 0;
            for (int v = 0; v < W; v++) {
                u64 kv = swin[v];
                if (((unsigned)((kv >> 6) & 0x3FFFull)) > inv)
                    off += (int)(kv & 63ull);
            }
        }
        if (off < MAXQ) {
            int boxLocal = 0x3FFF - (int)((key >> 6) & 0x3FFFull);
            u64 bm = g_bitmap[b*BPB + boxLocal];
            int cnt  = (int)(key & 63ull);
            int take = min(cnt, MAXQ - off);
            for (int t = 0; t < take; t++) {
                int d = __ffsll((long long)bm) - 1;   // depths asc = index asc
                bm &= bm - 1;
                ssel[off + t] = (boxLocal << 6) | d;
            }
        }
    }
    __syncthreads();

    // ---- P5: output ----
    if (tid < MAXQ) {
        const float DENOM = (float)(102.400001);
        float rx, ry, rz, pm;
        if (tid < filled) {
            int v = ssel[tid];
            int boxLocal = v >> 6;
            int dd = v & 63;
            int box_gid = b*BPB + boxLocal;
            int c = boxLocal / NBOX;
            int cam = b*NCAM + c;
            float4 bx = ((const float4*)boxes)[box_gid];
            CamData cd; load_cam(Kmat, Emat, cam, cd);
            cd.cx = (bx.x + bx.z)*0.5f;
            cd.cy = (bx.y + bx.w)*0.5f;
            float d = depth_of(dd);
            float X,Y,Z; fwd_point(cd, d, X, Y, Z);
            rx = fminf(fmaxf((X + 51.2f)/DENOM, 0.0f), 1.0f);
            ry = fminf(fmaxf((Y + 51.2f)/DENOM, 0.0f), 1.0f);
            rz = fminf(fmaxf((Z + 51.2f)/DENOM, 0.0f), 1.0f);
            pm = 0.0f;
        } else {
            float pad = fminf(fmaxf(51.2f/DENOM, 0.0f), 1.0f);
            rx = ry = rz = pad;
            pm = 1.0f;
        }
        int rbase = (b*MAXQ + tid)*3;
        out[rbase + 0] = rx;
        out[rbase + 1] = ry;
        out[rbase + 2] = rz;
        if (out_size >= NB*MAXQ*4)
            out[NB*MAXQ*3 + b*MAXQ + tid] = pm;
    }
}

// ---------------------------------------------------------------------------
extern "C" void kernel_launch(void* const* d_in, const int* in_sizes, int n_in,
                              void* d_out, int out_size)
{
    const float* boxes = (const float*)d_in[0];   // (8,6,900,4)
    const float* Kmat  = (const float*)d_in[1];   // (8,6,4,4)
    const float* Emat  = (const float*)d_in[2];   // (8,6,4,4)
    float* out = (float*)d_out;

    const int smem_bytes = BPB * 8;               // 43200 B (swin)
    cudaFuncSetAttribute(k_select, cudaFuncAttributeMaxDynamicSharedMemorySize,
                         smem_bytes);

    k_mask<<<(TOTAL_BOXES*4)/256, 256>>>(boxes, Kmat, Emat);
    k_select<<<NB, 1024, smem_bytes>>>(boxes, Kmat, Emat, out, out_size);
}